// round 1
// baseline (speedup 1.0000x reference)
#include <cuda_runtime.h>

// SSIM fused kernel for (16,3,512,512) fp32, 11x11 separable Gaussian window,
// VALID conv -> 502x502 outputs per channel-image, scalar mean output.

#define WS        11
#define TILE      32
#define HALO      (WS - 1)          // 10
#define IN_TILE   (TILE + HALO)     // 42
#define IMG_W     512
#define OUT_W     502
#define NTILES    16                // ceil(502/32)
#define NIMG      48                // 16 batch * 3 channels
#define NBLOCKS   (NIMG * NTILES * NTILES)

__device__ double g_partials[NBLOCKS];

__global__ __launch_bounds__(256)
void ssim_tile_kernel(const float* __restrict__ img1,
                      const float* __restrict__ img2,
                      const float* __restrict__ win)
{
    __shared__ float s1[IN_TILE][IN_TILE + 2];   // +2 pad: avoid bank conflicts
    __shared__ float s2[IN_TILE][IN_TILE + 2];
    __shared__ float sh[5][IN_TILE][TILE + 1];   // horizontal partial sums
    __shared__ double s_red[8];

    const int tid = threadIdx.x;
    const int z   = blockIdx.z;          // channel-image index 0..47
    const int c   = z % 3;
    const int ox  = blockIdx.x * TILE;
    const int oy  = blockIdx.y * TILE;

    // Reconstruct separable 1D factors from the (separable) 2D window.
    // w[i][j] == (w[i][5]/w[5][5]) * w[5][j] exactly for an outer-product window.
    const float* w = win + c * WS * WS;
    float gr[WS], gc[WS];
    const float inv_mid = 1.0f / w[5 * WS + 5];
    #pragma unroll
    for (int j = 0; j < WS; j++) {
        gr[j] = w[5 * WS + j];
        gc[j] = w[j * WS + 5] * inv_mid;
    }

    const float* base1 = img1 + (size_t)z * IMG_W * IMG_W;
    const float* base2 = img2 + (size_t)z * IMG_W * IMG_W;

    // ---- Load 42x42 halo tiles of both images ----
    for (int idx = tid; idx < IN_TILE * IN_TILE; idx += 256) {
        const int r  = idx / IN_TILE;
        const int cc = idx % IN_TILE;
        const int gy = oy + r;
        const int gx = ox + cc;
        float a = 0.0f, b = 0.0f;
        if (gy < IMG_W && gx < IMG_W) {
            a = base1[gy * IMG_W + gx];
            b = base2[gy * IMG_W + gx];
        }
        s1[r][cc] = a;
        s2[r][cc] = b;
    }
    __syncthreads();

    // ---- Horizontal separable pass: 5 fields, 42 rows x 32 cols ----
    for (int idx = tid; idx < IN_TILE * TILE; idx += 256) {
        const int r  = idx / TILE;
        const int cx = idx % TILE;
        float a1 = 0.f, a2 = 0.f, a11 = 0.f, a22 = 0.f, a12 = 0.f;
        #pragma unroll
        for (int j = 0; j < WS; j++) {
            const float g = gr[j];
            const float a = s1[r][cx + j];
            const float b = s2[r][cx + j];
            a1  += g * a;
            a2  += g * b;
            a11 += g * a * a;
            a22 += g * b * b;
            a12 += g * a * b;
        }
        sh[0][r][cx] = a1;
        sh[1][r][cx] = a2;
        sh[2][r][cx] = a11;
        sh[3][r][cx] = a22;
        sh[4][r][cx] = a12;
    }
    __syncthreads();

    // ---- Vertical pass + SSIM + accumulate ----
    double acc = 0.0;
    #pragma unroll
    for (int k = 0; k < (TILE * TILE) / 256; k++) {
        const int p = tid + k * 256;
        const int y = p / TILE;
        const int x = p % TILE;
        float m1 = 0.f, m2 = 0.f, e11 = 0.f, e22 = 0.f, e12 = 0.f;
        #pragma unroll
        for (int i = 0; i < WS; i++) {
            const float g = gc[i];
            m1  += g * sh[0][y + i][x];
            m2  += g * sh[1][y + i][x];
            e11 += g * sh[2][y + i][x];
            e22 += g * sh[3][y + i][x];
            e12 += g * sh[4][y + i][x];
        }
        const int gy = oy + y;
        const int gx = ox + x;
        if (gy < OUT_W && gx < OUT_W) {
            const float mu1s = m1 * m1;
            const float mu2s = m2 * m2;
            const float mu12 = m1 * m2;
            const float sg1  = e11 - mu1s;
            const float sg2  = e22 - mu2s;
            const float sg12 = e12 - mu12;
            const float num  = (2.0f * mu12) * (2.0f * sg12);
            const float den  = (mu1s + mu2s) * (sg1 + sg2);
            acc += (double)(num / den);
        }
    }

    // ---- Deterministic block reduction ----
    #pragma unroll
    for (int off = 16; off > 0; off >>= 1)
        acc += __shfl_down_sync(0xffffffffu, acc, off);
    if ((tid & 31) == 0) s_red[tid >> 5] = acc;
    __syncthreads();
    if (tid < 8) {
        double v = s_red[tid];
        #pragma unroll
        for (int off = 4; off > 0; off >>= 1)
            v += __shfl_down_sync(0xffu, v, off);
        if (tid == 0)
            g_partials[(z * NTILES + (int)blockIdx.y) * NTILES + (int)blockIdx.x] = v;
    }
}

__global__ __launch_bounds__(256)
void ssim_reduce_kernel(float* __restrict__ out)
{
    __shared__ double s[256];
    double acc = 0.0;
    for (int i = threadIdx.x; i < NBLOCKS; i += 256)
        acc += g_partials[i];
    s[threadIdx.x] = acc;
    __syncthreads();
    #pragma unroll
    for (int off = 128; off > 0; off >>= 1) {
        if (threadIdx.x < off) s[threadIdx.x] += s[threadIdx.x + off];
        __syncthreads();
    }
    if (threadIdx.x == 0) {
        const double total = (double)NIMG * (double)OUT_W * (double)OUT_W;
        out[0] = (float)(s[0] / total);
    }
}

extern "C" void kernel_launch(void* const* d_in, const int* in_sizes, int n_in,
                              void* d_out, int out_size)
{
    (void)in_sizes; (void)n_in; (void)out_size;
    const float* img1 = (const float*)d_in[0];
    const float* img2 = (const float*)d_in[1];
    const float* win  = (const float*)d_in[2];
    float* out = (float*)d_out;

    dim3 grid(NTILES, NTILES, NIMG);
    ssim_tile_kernel<<<grid, 256>>>(img1, img2, win);
    ssim_reduce_kernel<<<1, 256>>>(out);
}

// round 2
// speedup vs baseline: 1.6557x; 1.6557x over previous
#include <cuda_runtime.h>

// SSIM fused, (16,3,512,512) fp32, separable 11x11 Gaussian, VALID -> 502x502, mean.
// 4-field formulation: u=a+b, v=a-b; P=conv(u), M=conv(v), S=conv(u^2), D=conv(v^2)
// ssim = (P^2-M^2)(S-D-(P^2-M^2)) / ((P^2+M^2)(S+D-(P^2+M^2)))
// Packed f32x2 FMA throughout; register-blocked (x4) separable passes.

#define WS        11
#define TILE      32
#define IN_TILE   42
#define IMG_W     512
#define OUT_W     502
#define NTILES    16
#define NIMG      48
#define NBLOCKS   (NIMG * NTILES * NTILES)

typedef unsigned long long u64;

__device__ double g_partials[NBLOCKS];

__device__ __forceinline__ u64 pk2(float lo, float hi) {
    u64 r; asm("mov.b64 %0,{%1,%2};" : "=l"(r) : "f"(lo), "f"(hi)); return r;
}
__device__ __forceinline__ void upk2(float& lo, float& hi, u64 a) {
    asm("mov.b64 {%0,%1},%2;" : "=f"(lo), "=f"(hi) : "l"(a));
}
__device__ __forceinline__ u64 f2fma(u64 a, u64 b, u64 c) {
    u64 d; asm("fma.rn.f32x2 %0,%1,%2,%3;" : "=l"(d) : "l"(a), "l"(b), "l"(c)); return d;
}
__device__ __forceinline__ u64 f2mul(u64 a, u64 b) {
    u64 d; asm("mul.rn.f32x2 %0,%1,%2;" : "=l"(d) : "l"(a), "l"(b)); return d;
}

__global__ __launch_bounds__(256)
void ssim_tile_kernel(const float* __restrict__ img1,
                      const float* __restrict__ img2,
                      const float* __restrict__ win)
{
    __shared__ u64       s_uv[IN_TILE][IN_TILE + 1];   // packed (u,v): 42*43*8 = 14.4 KB
    __shared__ longlong2 sh[IN_TILE][TILE + 1];        // packed {(P,M),(S,D)}: 42*33*16 = 22.2 KB
    __shared__ double    s_red[8];

    const int tid = threadIdx.x;
    const int z   = blockIdx.z;
    const int c   = z % 3;
    const int ox  = blockIdx.x * TILE;
    const int oy  = blockIdx.y * TILE;

    // Separable 1D factors from the outer-product window (exact up to fp32 rounding).
    const float* w = win + c * WS * WS;
    const float inv_mid = 1.0f / w[5 * WS + 5];
    u64   ggr[WS];
    float gcf[WS];
    #pragma unroll
    for (int j = 0; j < WS; j++) {
        const float gr = w[5 * WS + j];
        ggr[j] = pk2(gr, gr);
        gcf[j] = w[j * WS + 5] * inv_mid;
    }

    const float* b1 = img1 + (size_t)z * IMG_W * IMG_W;
    const float* b2 = img2 + (size_t)z * IMG_W * IMG_W;

    // ---- Phase 0: load halo tile, pack (u, v) = (a+b, a-b) ----
    #pragma unroll
    for (int it = 0; it < 7; it++) {
        const int idx = tid + it * 256;
        if (idx < IN_TILE * IN_TILE) {
            const int r  = idx / IN_TILE;
            const int cc = idx - r * IN_TILE;
            const int gy = oy + r;
            const int gx = ox + cc;
            float a = 0.0f, b = 0.0f;
            if (gy < IMG_W && gx < IMG_W) {
                a = b1[gy * IMG_W + gx];
                b = b2[gy * IMG_W + gx];
            }
            s_uv[r][cc] = pk2(a + b, a - b);
        }
    }
    __syncthreads();

    // ---- Phase 1: horizontal pass, register-blocked x4 ----
    // 42 rows * 8 groups of 4 outputs = 336 work items
    #pragma unroll
    for (int it = 0; it < 2; it++) {
        const int wi = tid + it * 256;
        if (wi < IN_TILE * 8) {
            const int r  = wi >> 3;
            const int x0 = (wi & 7) * 4;
            u64 uv[14], sq[14];
            #pragma unroll
            for (int k = 0; k < 14; k++) {
                uv[k] = s_uv[r][x0 + k];
                sq[k] = f2mul(uv[k], uv[k]);
            }
            #pragma unroll
            for (int o = 0; o < 4; o++) {
                u64 a1 = 0ull, a2 = 0ull;
                #pragma unroll
                for (int j = 0; j < WS; j++) {
                    a1 = f2fma(ggr[j], uv[o + j], a1);   // (P, M)
                    a2 = f2fma(ggr[j], sq[o + j], a2);   // (S, D)
                }
                longlong2 t;
                t.x = (long long)a1;
                t.y = (long long)a2;
                sh[r][x0 + o] = t;
            }
        }
    }
    __syncthreads();

    // ---- Phase 2: vertical pass, register-blocked x4, + SSIM ----
    // 32 cols * 8 y-groups of 4 = 256 items: exactly one per thread.
    const int x  = tid & 31;
    const int y0 = (tid >> 5) * 4;

    u64 ggc[WS];
    #pragma unroll
    for (int i = 0; i < WS; i++) ggc[i] = pk2(gcf[i], gcf[i]);

    u64 tpm[14], tsd[14];
    #pragma unroll
    for (int k = 0; k < 14; k++) {
        const longlong2 t = sh[y0 + k][x];
        tpm[k] = (u64)t.x;
        tsd[k] = (u64)t.y;
    }

    double acc = 0.0;
    const bool xok = (ox + x) < OUT_W;
    #pragma unroll
    for (int o = 0; o < 4; o++) {
        u64 pm = 0ull, sd = 0ull;
        #pragma unroll
        for (int i = 0; i < WS; i++) {
            pm = f2fma(ggc[i], tpm[o + i], pm);
            sd = f2fma(ggc[i], tsd[o + i], sd);
        }
        float P, M, S, D;
        upk2(P, M, pm);
        upk2(S, D, sd);
        const float p2  = P * P;
        const float m2  = M * M;
        const float dd  = p2 - m2;          // 4*mu12
        const float aa  = p2 + m2;          // 2*(mu1^2+mu2^2)
        const float num = dd * ((S - D) - dd);
        const float den = aa * ((S + D) - aa);
        if (xok && (oy + y0 + o) < OUT_W)
            acc += (double)__fdividef(num, den);
    }

    // ---- Deterministic block reduction ----
    #pragma unroll
    for (int off = 16; off > 0; off >>= 1)
        acc += __shfl_down_sync(0xffffffffu, acc, off);
    if ((tid & 31) == 0) s_red[tid >> 5] = acc;
    __syncthreads();
    if (tid < 8) {
        double v = s_red[tid];
        #pragma unroll
        for (int off = 4; off > 0; off >>= 1)
            v += __shfl_down_sync(0xffu, v, off);
        if (tid == 0)
            g_partials[(z * NTILES + (int)blockIdx.y) * NTILES + (int)blockIdx.x] = v;
    }
}

__global__ __launch_bounds__(1024)
void ssim_reduce_kernel(float* __restrict__ out)
{
    __shared__ double s[1024];
    double acc = 0.0;
    for (int i = threadIdx.x; i < NBLOCKS; i += 1024)
        acc += g_partials[i];
    s[threadIdx.x] = acc;
    __syncthreads();
    #pragma unroll
    for (int off = 512; off > 0; off >>= 1) {
        if (threadIdx.x < off) s[threadIdx.x] += s[threadIdx.x + off];
        __syncthreads();
    }
    if (threadIdx.x == 0) {
        const double total = (double)NIMG * (double)OUT_W * (double)OUT_W;
        out[0] = (float)(s[0] / total);
    }
}

extern "C" void kernel_launch(void* const* d_in, const int* in_sizes, int n_in,
                              void* d_out, int out_size)
{
    (void)in_sizes; (void)n_in; (void)out_size;
    const float* img1 = (const float*)d_in[0];
    const float* img2 = (const float*)d_in[1];
    const float* win  = (const float*)d_in[2];
    float* out = (float*)d_out;

    dim3 grid(NTILES, NTILES, NIMG);
    ssim_tile_kernel<<<grid, 256>>>(img1, img2, win);
    ssim_reduce_kernel<<<1, 1024>>>(out);
}